// round 14
// baseline (speedup 1.0000x reference)
#include <cuda_runtime.h>
#include <math.h>
#include <stdint.h>

// Problem constants (fixed by the dataset)
#define MAXN 50000
#define MAXE 600000
#define HD   128
#define OUTD 40
#define NITER 5
#define GAMMA_C 0.1f
#define EPS_C   0.1f

// ---------------- scratch (device globals: no allocation allowed) -----------
__device__ float g_h[MAXN * HD];        // current node features x
__device__ float g_neigh[MAXN * HD];    // x @ W_lin^T
__device__ float g_zb[MAXN * HD];       // x @ A^T + b_conv
__device__ float g_Bemb[HD * HD];       // B[k][j] = W_emb[j][k]
__device__ float g_Bc[HD * 256];        // [k][j<128]=W_lin[j][k]; [k][128+j]=A[j][k]
__device__ float g_biasc[256];          // [0..127]=0, [128..255]=b_conv
__device__ int   g_rowstart[MAXN + 1];
__device__ int   g_cursor[MAXN];
__device__ int2  g_epack[MAXE];         // {src, __float_as_int(weight)}
__device__ int   g_part[256];

// ---------------- f32x2 helpers (documented sm_103a pattern) -----------------
__device__ __forceinline__ unsigned long long pack2(float a) {
    unsigned long long r;
    asm("mov.b64 %0,{%1,%1};" : "=l"(r) : "f"(a));
    return r;
}
__device__ __forceinline__ void ffma2(unsigned long long& d,
                                      unsigned long long a,
                                      unsigned long long b) {
    asm("fma.rn.f32x2 %0,%1,%2,%0;" : "+l"(d) : "l"(a), "l"(b));
}
__device__ __forceinline__ void unpack2(unsigned long long v, float& lo, float& hi) {
    asm("mov.b64 {%0,%1},%2;" : "=f"(lo), "=f"(hi) : "l"(v));
}
// inf-safe fast tanh: 2 MUFU + 3 flops, rel err ~1e-6
__device__ __forceinline__ float tanh_fast(float x) {
    float e = __expf(2.0f * x);
    return 1.0f - __fdividef(2.0f, e + 1.0f);
}
// 16B global->shared async copy (sm_80 PTX; legal at compute_103)
__device__ __forceinline__ void cp_async16(float* s, const float* g) {
    uint32_t sa = (uint32_t)__cvta_generic_to_shared(s);
    asm volatile("cp.async.cg.shared.global [%0], [%1], 16;" :: "r"(sa), "l"(g));
}
#define CP_COMMIT() asm volatile("cp.async.commit_group;")
#define CP_WAIT0()  asm volatile("cp.async.wait_group 0;" ::: "memory")

// ---------------- weight preprocessing + rowstart zero -----------------------
__global__ void precompute_kernel(const float* __restrict__ W_emb,
                                  const float* __restrict__ W_lin,
                                  const float* __restrict__ W_anti,
                                  const float* __restrict__ b_conv,
                                  int N1) {
    int tid = blockIdx.x * blockDim.x + threadIdx.x;
    int nt  = gridDim.x * blockDim.x;
    for (int i = tid; i < N1; i += nt) g_rowstart[i] = 0;
    for (int idx = tid; idx < HD * HD; idx += nt) {
        int k = idx >> 7, j = idx & 127;
        g_Bemb[k * HD + j] = W_emb[j * HD + k];
    }
    for (int idx = tid; idx < HD * 256; idx += nt) {
        int k = idx >> 8, j = idx & 255;
        float v;
        if (j < 128) {
            v = W_lin[j * HD + k];
        } else {
            int jj = j - 128;
            v = W_anti[jj * HD + k] - W_anti[k * HD + jj];
            if (jj == k) v -= GAMMA_C;
        }
        g_Bc[k * 256 + j] = v;
    }
    for (int j = tid; j < 256; j += nt)
        g_biasc[j] = (j < 128) ? 0.0f : b_conv[j - 128];
}

// ---------------- CSR build (counting sort by dst; edge_index is INT32) ------
__global__ void count_kernel(const int* __restrict__ ei, int E, int N) {
    int i = blockIdx.x * blockDim.x + threadIdx.x;
    for (; i < E; i += gridDim.x * blockDim.x) {
        int d = ei[E + i];
        if (d >= 0 && d < N) atomicAdd(&g_rowstart[d + 1], 1);
    }
}
#define SCAN_NB 196
__global__ void scan_partial_kernel(int n) {    // grid SCAN_NB x 256
    __shared__ int sd[256];
    int t = threadIdx.x, i = blockIdx.x * 256 + t;
    sd[t] = (i < n) ? g_rowstart[i] : 0;
    __syncthreads();
    for (int off = 128; off; off >>= 1) {
        if (t < off) sd[t] += sd[t + off];
        __syncthreads();
    }
    if (t == 0) g_part[blockIdx.x] = sd[0];
}
__global__ void scan_offsets_kernel() {          // 1 x 256
    __shared__ int sd[256];
    int t = threadIdx.x;
    int v = (t < SCAN_NB) ? g_part[t] : 0;
    sd[t] = v;
    __syncthreads();
    for (int off = 1; off < 256; off <<= 1) {
        int u = (t >= off) ? sd[t - off] : 0;
        __syncthreads();
        sd[t] += u;
        __syncthreads();
    }
    g_part[t] = sd[t] - v;                       // exclusive
}
__global__ void scan_apply_kernel(int n, int N) { // grid SCAN_NB x 256
    __shared__ int sd[256];
    int t = threadIdx.x, i = blockIdx.x * 256 + t;
    int v = (i < n) ? g_rowstart[i] : 0;
    sd[t] = v;
    __syncthreads();
    for (int off = 1; off < 256; off <<= 1) {
        int u = (t >= off) ? sd[t - off] : 0;
        __syncthreads();
        sd[t] += u;
        __syncthreads();
    }
    int val = g_part[blockIdx.x] + sd[t];        // inclusive global
    if (i < n) {
        g_rowstart[i] = val;
        if (i < N) g_cursor[i] = val;
    }
}
__global__ void sort_kernel(const int* __restrict__ ei,
                            const float* __restrict__ ew, int E, int N) {
    int i = blockIdx.x * blockDim.x + threadIdx.x;
    for (; i < E; i += gridDim.x * blockDim.x) {
        int d = ei[E + i];
        int s = ei[i];
        if (d < 0 || d >= N || s < 0 || s >= N) continue;
        int pos = atomicAdd(&g_cursor[d], 1);
        g_epack[pos] = make_int2(s, __float_as_int(ew[i]));
    }
}

// ---------------- embedding GEMM (FFMA2): g_h = x @ W_emb^T + b_emb ----------
__global__ void __launch_bounds__(256, 2) embed_gemm_kernel(const float* __restrict__ X,
                                                            const float* __restrict__ bias,
                                                            int M) {
    __shared__ float sX[64 * HD];        // 32 KB
    __shared__ float sB[8 * HD];         // 4 KB chunk
    const int tid = threadIdx.x;
    const int tx = tid & 31, ty = tid >> 5;
    const int row0 = blockIdx.x * 64;

#pragma unroll
    for (int j = 0; j < 8; j++) {
        int f = tid + j * 256;
        int r = f >> 5, c = (f & 31) << 2;
        float4 v = make_float4(0.f, 0.f, 0.f, 0.f);
        if (row0 + r < M) v = *(const float4*)(X + (size_t)(row0 + r) * HD + c);
        *(float4*)(sX + r * HD + c) = v;
    }

    unsigned long long acc[8][2];
#pragma unroll
    for (int i = 0; i < 8; i++) { acc[i][0] = 0ull; acc[i][1] = 0ull; }

    for (int kc = 0; kc < 16; kc++) {
        ((float4*)sB)[tid] = ((const float4*)g_Bemb)[kc * 256 + tid];
        __syncthreads();
#pragma unroll
        for (int k = 0; k < 8; k += 2) {
            float2 a2[8];
#pragma unroll
            for (int i = 0; i < 8; i++)
                a2[i] = *(const float2*)(sX + (ty * 8 + i) * HD + kc * 8 + k);
#pragma unroll
            for (int kk = 0; kk < 2; kk++) {
                ulonglong2 b0 = *(const ulonglong2*)(sB + (k + kk) * HD + tx * 4);
#pragma unroll
                for (int i = 0; i < 8; i++) {
                    unsigned long long ap = pack2(kk ? a2[i].y : a2[i].x);
                    ffma2(acc[i][0], ap, b0.x);
                    ffma2(acc[i][1], ap, b0.y);
                }
            }
        }
        __syncthreads();
    }

    float4 bs = *(const float4*)(bias + tx * 4);
#pragma unroll
    for (int i = 0; i < 8; i++) {
        int r = row0 + ty * 8 + i;
        if (r >= M) break;
        float4 v;
        unpack2(acc[i][0], v.x, v.y);
        unpack2(acc[i][1], v.z, v.w);
        v.x += bs.x; v.y += bs.y; v.z += bs.z; v.w += bs.w;
        *(float4*)(g_h + (size_t)r * HD + tx * 4) = v;
    }
}

// --- conv (FFMA2), persistent + cp.async double-buffered X -------------------
// 768 threads (24 warps = 6/SMSP, was 4/SMSP in R13), 4 rows x 8 cols per
// thread -- same column width (pack2/FFMA2 ratio unchanged; R12 showed
// narrowing columns hurts). smem = 128KB B + 2x48KB X = 224KB, 1 CTA/SM.
#define CONV_TB   768
#define TROWS     96
#define CONV_SMEM ((128 * 256 + 2 * TROWS * 128) * (int)sizeof(float))  // 224 KB

__global__ void __launch_bounds__(CONV_TB, 1) conv_gemm_kernel(int M, int ntiles) {
    extern __shared__ float smem[];
    float* sB = smem;                    // 128 k x 256 cols
    float* sX = smem + 128 * 256;        // 2 x (96 x 128)
    const int tid = threadIdx.x;
    const int tx = tid & 31, ty = tid >> 5;   // ty in [0,24): 4 rows each

    // load full B once (8192 float4)
    for (int f = tid; f < 8192; f += CONV_TB)
        ((float4*)sB)[f] = ((const float4*)g_Bc)[f];

    int tile = blockIdx.x;
    int buf = 0;
    if (tile < ntiles) {
        int row0 = tile * TROWS;
#pragma unroll
        for (int j = 0; j < 4; j++) {
            int f = tid + j * CONV_TB, r = f >> 5, c = (f & 31) << 2;
            int gr = row0 + r; if (gr > M - 1) gr = M - 1;
            cp_async16(sX + r * HD + c, g_h + (size_t)gr * HD + c);
        }
        CP_COMMIT();
        CP_WAIT0();
    }
    __syncthreads();

    while (tile < ntiles) {
        const int next = tile + gridDim.x;
        const float* sXc = sX + buf * (TROWS * HD);
        float*       sXn = sX + (buf ^ 1) * (TROWS * HD);
        if (next < ntiles) {                      // prefetch next tile
            int row0n = next * TROWS;
#pragma unroll
            for (int j = 0; j < 4; j++) {
                int f = tid + j * CONV_TB, r = f >> 5, c = (f & 31) << 2;
                int gr = row0n + r; if (gr > M - 1) gr = M - 1;
                cp_async16(sXn + r * HD + c, g_h + (size_t)gr * HD + c);
            }
            CP_COMMIT();
        }

        unsigned long long acc[4][2][2];
#pragma unroll
        for (int i = 0; i < 4; i++) {
            acc[i][0][0] = 0ull; acc[i][0][1] = 0ull;
            acc[i][1][0] = 0ull; acc[i][1][1] = 0ull;
        }

        const float* xr = sXc + ty * 4 * HD;
#pragma unroll 4
        for (int k = 0; k < HD; k += 2) {
            float2 a2[4];
#pragma unroll
            for (int i = 0; i < 4; i++)
                a2[i] = *(const float2*)(xr + i * HD + k);
#pragma unroll
            for (int kk = 0; kk < 2; kk++) {
                const float* bw = sB + (k + kk) * 256 + tx * 4;
                ulonglong2 b0 = *(const ulonglong2*)(bw);
                ulonglong2 b1 = *(const ulonglong2*)(bw + 128);
#pragma unroll
                for (int i = 0; i < 4; i++) {
                    unsigned long long ap = pack2(kk ? a2[i].y : a2[i].x);
                    ffma2(acc[i][0][0], ap, b0.x);
                    ffma2(acc[i][0][1], ap, b0.y);
                    ffma2(acc[i][1][0], ap, b1.x);
                    ffma2(acc[i][1][1], ap, b1.y);
                }
            }
        }

        const int row0 = tile * TROWS;
        float4 bs = *(const float4*)(g_biasc + 128 + tx * 4);
#pragma unroll
        for (int i = 0; i < 4; i++) {
            int r = row0 + ty * 4 + i;
            if (r < M) {
                float4 v0, v1;
                unpack2(acc[i][0][0], v0.x, v0.y);
                unpack2(acc[i][0][1], v0.z, v0.w);
                unpack2(acc[i][1][0], v1.x, v1.y);
                unpack2(acc[i][1][1], v1.z, v1.w);
                v1.x += bs.x; v1.y += bs.y; v1.z += bs.z; v1.w += bs.w;
                *(float4*)(g_neigh + (size_t)r * HD + tx * 4) = v0;
                *(float4*)(g_zb    + (size_t)r * HD + tx * 4) = v1;
            }
        }

        if (next < ntiles) CP_WAIT0();
        __syncthreads();                           // buffer handoff
        tile = next; buf ^= 1;
    }
}

// ---------------- aggregation + tanh residual update (warp per node) ---------
__global__ void __launch_bounds__(256) agg_update_kernel(int N) {
    int node = (blockIdx.x * blockDim.x + threadIdx.x) >> 5;
    int lane = threadIdx.x & 31;
    if (node >= N) return;
    const float4* neigh = (const float4*)g_neigh;
    const float4* zb    = (const float4*)g_zb;
    float4*       hv    = (float4*)g_h;

    int s = g_rowstart[node];
    int e = g_rowstart[node + 1];
    float4 acc = make_float4(0.f, 0.f, 0.f, 0.f);
    int i = s;
    for (; i + 4 <= e; i += 4) {                    // MLP=4 gather
        int2 p0 = g_epack[i],     p1 = g_epack[i + 1];
        int2 p2 = g_epack[i + 2], p3 = g_epack[i + 3];
        float4 v0 = neigh[(size_t)p0.x * 32 + lane];
        float4 v1 = neigh[(size_t)p1.x * 32 + lane];
        float4 v2 = neigh[(size_t)p2.x * 32 + lane];
        float4 v3 = neigh[(size_t)p3.x * 32 + lane];
        float w0 = __int_as_float(p0.y), w1 = __int_as_float(p1.y);
        float w2 = __int_as_float(p2.y), w3 = __int_as_float(p3.y);
        acc.x += w0*v0.x + w1*v1.x + w2*v2.x + w3*v3.x;
        acc.y += w0*v0.y + w1*v1.y + w2*v2.y + w3*v3.y;
        acc.z += w0*v0.z + w1*v1.z + w2*v2.z + w3*v3.z;
        acc.w += w0*v0.w + w1*v1.w + w2*v2.w + w3*v3.w;
    }
    for (; i < e; i++) {
        int2 p = g_epack[i];
        float w = __int_as_float(p.y);
        float4 v = neigh[(size_t)p.x * 32 + lane];
        acc.x += w * v.x; acc.y += w * v.y; acc.z += w * v.z; acc.w += w * v.w;
    }
    float4 c = zb[(size_t)node * 32 + lane];
    c.x += acc.x; c.y += acc.y; c.z += acc.z; c.w += acc.w;
    float4 xo = hv[(size_t)node * 32 + lane];
    xo.x += EPS_C * tanh_fast(c.x);
    xo.y += EPS_C * tanh_fast(c.y);
    xo.z += EPS_C * tanh_fast(c.z);
    xo.w += EPS_C * tanh_fast(c.w);
    hv[(size_t)node * 32 + lane] = xo;
}

// ---------------- readout: out[M x 40] = h @ W_out^T + b_out -----------------
__global__ void __launch_bounds__(128) readout_kernel(const float* __restrict__ W,
                                                      const float* __restrict__ b,
                                                      float* __restrict__ out,
                                                      int M) {
    __shared__ float hs[32 * 132];
    __shared__ float Wt[128 * 41];
    int tid = threadIdx.x;
    int row0 = blockIdx.x * 32;
#pragma unroll
    for (int j = 0; j < 8; j++) {
        int f = tid + j * 128;
        int r = f >> 5;
        int c = (f & 31) << 2;
        float4 v = make_float4(0.f, 0.f, 0.f, 0.f);
        if (row0 + r < M) v = *(const float4*)(g_h + (size_t)(row0 + r) * HD + c);
        *(float4*)(hs + r * 132 + c) = v;
    }
    for (int f = tid; f < OUTD * HD; f += 128) {
        int c = f / HD, k = f % HD;
        Wt[k * 41 + c] = W[c * HD + k];
    }
    __syncthreads();

    int tx = tid & 7;
    int ty = tid >> 3;
    float acc[2][5] = {{0.f,0.f,0.f,0.f,0.f},{0.f,0.f,0.f,0.f,0.f}};
#pragma unroll 4
    for (int k = 0; k < HD; k++) {
        float a0 = hs[(ty * 2) * 132 + k];
        float a1 = hs[(ty * 2 + 1) * 132 + k];
        const float* w = Wt + k * 41 + tx * 5;
#pragma unroll
        for (int j = 0; j < 5; j++) {
            float wv = w[j];
            acc[0][j] += a0 * wv;
            acc[1][j] += a1 * wv;
        }
    }
#pragma unroll
    for (int i = 0; i < 2; i++) {
        int r = row0 + ty * 2 + i;
        if (r < M) {
#pragma unroll
            for (int j = 0; j < 5; j++)
                out[(size_t)r * OUTD + tx * 5 + j] = acc[i][j] + b[tx * 5 + j];
        }
    }
}

// ---------------- launch ------------------------------------------------------
extern "C" void kernel_launch(void* const* d_in, const int* in_sizes, int n_in,
                              void* d_out, int out_size) {
    const float* x      = (const float*)d_in[0];
    const int*   ei     = (const int*)d_in[1];     // int32 (JAX x64 disabled)
    const float* ew     = (const float*)d_in[2];
    const float* W_emb  = (const float*)d_in[3];
    const float* b_emb  = (const float*)d_in[4];
    const float* W_lin  = (const float*)d_in[5];
    const float* W_anti = (const float*)d_in[6];
    const float* b_conv = (const float*)d_in[7];
    const float* W_out  = (const float*)d_in[8];
    const float* b_out  = (const float*)d_in[9];
    float*       out    = (float*)d_out;

    const int M = in_sizes[0] / HD;
    const int E = in_sizes[2];
    const int gb = (M + 63) / 64;
    const int ntiles = (M + TROWS - 1) / TROWS;

    // one persistent CTA per SM; 224 KB smem opt-in (host calls, capture-legal)
    static int nsm = 0;
    if (!nsm) {
        cudaDeviceGetAttribute(&nsm, cudaDevAttrMultiProcessorCount, 0);
        if (nsm <= 0) nsm = 148;
        cudaFuncSetAttribute((const void*)conv_gemm_kernel,
                             cudaFuncAttributeMaxDynamicSharedMemorySize, CONV_SMEM);
    }

    // Launch order arranged so conv_gemm_kernel is launch #4 (ncu capture slot).
    // (1) weights + rowstart zero
    precompute_kernel<<<64, 256>>>(W_emb, W_lin, W_anti, b_conv, M + 1);
    // (2) degree histogram (needs zeroed rowstart)
    count_kernel<<<(E + 255) / 256, 256>>>(ei, E, M);
    // (3) embedding (needs precompute)
    embed_gemm_kernel<<<gb, 256>>>(x, b_emb, M);
    // (4) first conv (needs embed)  <-- ncu capture lands here
    conv_gemm_kernel<<<nsm, CONV_TB, CONV_SMEM>>>(M, ntiles);
    // (5-8) finish CSR build
    scan_partial_kernel<<<SCAN_NB, 256>>>(M + 1);
    scan_offsets_kernel<<<1, 256>>>();
    scan_apply_kernel<<<SCAN_NB, 256>>>(M + 1, M);
    sort_kernel<<<(E + 255) / 256, 256>>>(ei, ew, E, M);
    // (9) first aggregation
    agg_update_kernel<<<(M + 7) / 8, 256>>>(M);

    // iterations 2..5
    for (int it = 1; it < NITER; it++) {
        conv_gemm_kernel<<<nsm, CONV_TB, CONV_SMEM>>>(M, ntiles);
        agg_update_kernel<<<(M + 7) / 8, 256>>>(M);
    }

    // readout
    readout_kernel<<<(M + 31) / 32, 128>>>(W_out, b_out, out, M);
}

// round 15
// speedup vs baseline: 1.0821x; 1.0821x over previous
#include <cuda_runtime.h>
#include <math.h>
#include <stdint.h>

// Problem constants (fixed by the dataset)
#define MAXN 50000
#define MAXE 600000
#define HD   128
#define OUTD 40
#define NITER 5
#define GAMMA_C 0.1f
#define EPS_C   0.1f

// ---------------- scratch (device globals: no allocation allowed) -----------
__device__ float g_h[MAXN * HD];        // current node features x
__device__ float g_neigh[MAXN * HD];    // x @ W_lin^T
__device__ float g_zb[MAXN * HD];       // x @ A^T + b_conv
__device__ float g_Bemb[HD * HD];       // B[k][j] = W_emb[j][k]
__device__ float g_Bc[HD * 256];        // [k][j<128]=W_lin[j][k]; [k][128+j]=A[j][k]
__device__ float g_biasc[256];          // [0..127]=0, [128..255]=b_conv
__device__ int   g_rowstart[MAXN + 1];
__device__ int   g_cursor[MAXN];
__device__ int2  g_epack[MAXE];         // {src, __float_as_int(weight)}
__device__ int   g_part[256];

// ---------------- f32x2 helpers (documented sm_103a pattern) -----------------
__device__ __forceinline__ unsigned long long pack2(float a) {
    unsigned long long r;
    asm("mov.b64 %0,{%1,%1};" : "=l"(r) : "f"(a));
    return r;
}
__device__ __forceinline__ void ffma2(unsigned long long& d,
                                      unsigned long long a,
                                      unsigned long long b) {
    asm("fma.rn.f32x2 %0,%1,%2,%0;" : "+l"(d) : "l"(a), "l"(b));
}
__device__ __forceinline__ void unpack2(unsigned long long v, float& lo, float& hi) {
    asm("mov.b64 {%0,%1},%2;" : "=f"(lo), "=f"(hi) : "l"(v));
}
// inf-safe fast tanh: 2 MUFU + 3 flops, rel err ~1e-6
__device__ __forceinline__ float tanh_fast(float x) {
    float e = __expf(2.0f * x);
    return 1.0f - __fdividef(2.0f, e + 1.0f);
}
// 16B global->shared async copy (sm_80 PTX; legal at compute_103)
__device__ __forceinline__ void cp_async16(float* s, const float* g) {
    uint32_t sa = (uint32_t)__cvta_generic_to_shared(s);
    asm volatile("cp.async.cg.shared.global [%0], [%1], 16;" :: "r"(sa), "l"(g));
}
#define CP_COMMIT() asm volatile("cp.async.commit_group;")
#define CP_WAIT0()  asm volatile("cp.async.wait_group 0;" ::: "memory")

// ---------------- weight preprocessing + rowstart zero -----------------------
__global__ void precompute_kernel(const float* __restrict__ W_emb,
                                  const float* __restrict__ W_lin,
                                  const float* __restrict__ W_anti,
                                  const float* __restrict__ b_conv,
                                  int N1) {
    int tid = blockIdx.x * blockDim.x + threadIdx.x;
    int nt  = gridDim.x * blockDim.x;
    for (int i = tid; i < N1; i += nt) g_rowstart[i] = 0;
    for (int idx = tid; idx < HD * HD; idx += nt) {
        int k = idx >> 7, j = idx & 127;
        g_Bemb[k * HD + j] = W_emb[j * HD + k];
    }
    for (int idx = tid; idx < HD * 256; idx += nt) {
        int k = idx >> 8, j = idx & 255;
        float v;
        if (j < 128) {
            v = W_lin[j * HD + k];
        } else {
            int jj = j - 128;
            v = W_anti[jj * HD + k] - W_anti[k * HD + jj];
            if (jj == k) v -= GAMMA_C;
        }
        g_Bc[k * 256 + j] = v;
    }
    for (int j = tid; j < 256; j += nt)
        g_biasc[j] = (j < 128) ? 0.0f : b_conv[j - 128];
}

// ---------------- CSR build (counting sort by dst; edge_index is INT32) ------
__global__ void count_kernel(const int* __restrict__ ei, int E, int N) {
    int i = blockIdx.x * blockDim.x + threadIdx.x;
    for (; i < E; i += gridDim.x * blockDim.x) {
        int d = ei[E + i];
        if (d >= 0 && d < N) atomicAdd(&g_rowstart[d + 1], 1);
    }
}
#define SCAN_NB 196
__global__ void scan_partial_kernel(int n) {    // grid SCAN_NB x 256
    __shared__ int sd[256];
    int t = threadIdx.x, i = blockIdx.x * 256 + t;
    sd[t] = (i < n) ? g_rowstart[i] : 0;
    __syncthreads();
    for (int off = 128; off; off >>= 1) {
        if (t < off) sd[t] += sd[t + off];
        __syncthreads();
    }
    if (t == 0) g_part[blockIdx.x] = sd[0];
}
// merged: per-block offset reduction over g_part[0..bid) + local scan + apply
__global__ void scan_apply_kernel(int n, int N) { // grid SCAN_NB x 256
    __shared__ int sd[256];
    __shared__ int soff[256];
    int t = threadIdx.x, i = blockIdx.x * 256 + t;
    // block offset = sum of g_part[j] for j < blockIdx.x
    soff[t] = (t < blockIdx.x) ? g_part[t] : 0;
    __syncthreads();
    for (int off = 128; off; off >>= 1) {
        if (t < off) soff[t] += soff[t + off];
        __syncthreads();
    }
    int blockoff = soff[0];

    int v = (i < n) ? g_rowstart[i] : 0;
    sd[t] = v;
    __syncthreads();
    for (int off = 1; off < 256; off <<= 1) {
        int u = (t >= off) ? sd[t - off] : 0;
        __syncthreads();
        sd[t] += u;
        __syncthreads();
    }
    int val = blockoff + sd[t];                  // inclusive global
    if (i < n) {
        g_rowstart[i] = val;
        if (i < N) g_cursor[i] = val;
    }
}
__global__ void sort_kernel(const int* __restrict__ ei,
                            const float* __restrict__ ew, int E, int N) {
    int i = blockIdx.x * blockDim.x + threadIdx.x;
    for (; i < E; i += gridDim.x * blockDim.x) {
        int d = ei[E + i];
        int s = ei[i];
        if (d < 0 || d >= N || s < 0 || s >= N) continue;
        int pos = atomicAdd(&g_cursor[d], 1);
        g_epack[pos] = make_int2(s, __float_as_int(ew[i]));
    }
}

// ---------------- embedding GEMM (FFMA2): g_h = x @ W_emb^T + b_emb ----------
__global__ void __launch_bounds__(256, 2) embed_gemm_kernel(const float* __restrict__ X,
                                                            const float* __restrict__ bias,
                                                            int M) {
    __shared__ float sX[64 * HD];        // 32 KB
    __shared__ float sB[8 * HD];         // 4 KB chunk
    const int tid = threadIdx.x;
    const int tx = tid & 31, ty = tid >> 5;
    const int row0 = blockIdx.x * 64;

#pragma unroll
    for (int j = 0; j < 8; j++) {
        int f = tid + j * 256;
        int r = f >> 5, c = (f & 31) << 2;
        float4 v = make_float4(0.f, 0.f, 0.f, 0.f);
        if (row0 + r < M) v = *(const float4*)(X + (size_t)(row0 + r) * HD + c);
        *(float4*)(sX + r * HD + c) = v;
    }

    unsigned long long acc[8][2];
#pragma unroll
    for (int i = 0; i < 8; i++) { acc[i][0] = 0ull; acc[i][1] = 0ull; }

    for (int kc = 0; kc < 16; kc++) {
        ((float4*)sB)[tid] = ((const float4*)g_Bemb)[kc * 256 + tid];
        __syncthreads();
#pragma unroll
        for (int k = 0; k < 8; k += 2) {
            float2 a2[8];
#pragma unroll
            for (int i = 0; i < 8; i++)
                a2[i] = *(const float2*)(sX + (ty * 8 + i) * HD + kc * 8 + k);
#pragma unroll
            for (int kk = 0; kk < 2; kk++) {
                ulonglong2 b0 = *(const ulonglong2*)(sB + (k + kk) * HD + tx * 4);
#pragma unroll
                for (int i = 0; i < 8; i++) {
                    unsigned long long ap = pack2(kk ? a2[i].y : a2[i].x);
                    ffma2(acc[i][0], ap, b0.x);
                    ffma2(acc[i][1], ap, b0.y);
                }
            }
        }
        __syncthreads();
    }

    float4 bs = *(const float4*)(bias + tx * 4);
#pragma unroll
    for (int i = 0; i < 8; i++) {
        int r = row0 + ty * 8 + i;
        if (r >= M) break;
        float4 v;
        unpack2(acc[i][0], v.x, v.y);
        unpack2(acc[i][1], v.z, v.w);
        v.x += bs.x; v.y += bs.y; v.z += bs.z; v.w += bs.w;
        *(float4*)(g_h + (size_t)r * HD + tx * 4) = v;
    }
}

// --- conv (FFMA2), persistent + cp.async double-buffered X (R13 config) ------
// 512 threads (16 warps = 4/SMSP), 6 rows x 8 cols per thread, 128 regs.
// smem = 128KB B + 2x48KB X = 224KB, 1 CTA/SM. R12/R14 mapped the design
// space: narrower columns or more warps both regress (pack2/alu overhead).
#define CONV_TB   512
#define TROWS     96
#define CONV_SMEM ((128 * 256 + 2 * TROWS * 128) * (int)sizeof(float))  // 224 KB

__global__ void __launch_bounds__(CONV_TB, 1) conv_gemm_kernel(int M, int ntiles) {
    extern __shared__ float smem[];
    float* sB = smem;                    // 128 k x 256 cols
    float* sX = smem + 128 * 256;        // 2 x (96 x 128)
    const int tid = threadIdx.x;
    const int tx = tid & 31, ty = tid >> 5;   // ty in [0,16): 6 rows each

    // load full B once (8192 float4)
#pragma unroll
    for (int j = 0; j < 16; j++)
        ((float4*)sB)[tid + j * 512] = ((const float4*)g_Bc)[tid + j * 512];

    int tile = blockIdx.x;
    int buf = 0;
    if (tile < ntiles) {
        int row0 = tile * TROWS;
#pragma unroll
        for (int j = 0; j < 6; j++) {
            int f = tid + j * 512, r = f >> 5, c = (f & 31) << 2;
            int gr = row0 + r; if (gr > M - 1) gr = M - 1;
            cp_async16(sX + r * HD + c, g_h + (size_t)gr * HD + c);
        }
        CP_COMMIT();
        CP_WAIT0();
    }
    __syncthreads();

    while (tile < ntiles) {
        const int next = tile + gridDim.x;
        const float* sXc = sX + buf * (TROWS * HD);
        float*       sXn = sX + (buf ^ 1) * (TROWS * HD);
        if (next < ntiles) {                      // prefetch next tile
            int row0n = next * TROWS;
#pragma unroll
            for (int j = 0; j < 6; j++) {
                int f = tid + j * 512, r = f >> 5, c = (f & 31) << 2;
                int gr = row0n + r; if (gr > M - 1) gr = M - 1;
                cp_async16(sXn + r * HD + c, g_h + (size_t)gr * HD + c);
            }
            CP_COMMIT();
        }

        unsigned long long acc[6][2][2];
#pragma unroll
        for (int i = 0; i < 6; i++) {
            acc[i][0][0] = 0ull; acc[i][0][1] = 0ull;
            acc[i][1][0] = 0ull; acc[i][1][1] = 0ull;
        }

        const float* xr = sXc + ty * 6 * HD;
#pragma unroll 4
        for (int k = 0; k < HD; k += 2) {
            float2 a2[6];
#pragma unroll
            for (int i = 0; i < 6; i++)
                a2[i] = *(const float2*)(xr + i * HD + k);
#pragma unroll
            for (int kk = 0; kk < 2; kk++) {
                const float* bw = sB + (k + kk) * 256 + tx * 4;
                ulonglong2 b0 = *(const ulonglong2*)(bw);
                ulonglong2 b1 = *(const ulonglong2*)(bw + 128);
#pragma unroll
                for (int i = 0; i < 6; i++) {
                    unsigned long long ap = pack2(kk ? a2[i].y : a2[i].x);
                    ffma2(acc[i][0][0], ap, b0.x);
                    ffma2(acc[i][0][1], ap, b0.y);
                    ffma2(acc[i][1][0], ap, b1.x);
                    ffma2(acc[i][1][1], ap, b1.y);
                }
            }
        }

        const int row0 = tile * TROWS;
        float4 bs = *(const float4*)(g_biasc + 128 + tx * 4);
#pragma unroll
        for (int i = 0; i < 6; i++) {
            int r = row0 + ty * 6 + i;
            if (r < M) {
                float4 v0, v1;
                unpack2(acc[i][0][0], v0.x, v0.y);
                unpack2(acc[i][0][1], v0.z, v0.w);
                unpack2(acc[i][1][0], v1.x, v1.y);
                unpack2(acc[i][1][1], v1.z, v1.w);
                v1.x += bs.x; v1.y += bs.y; v1.z += bs.z; v1.w += bs.w;
                *(float4*)(g_neigh + (size_t)r * HD + tx * 4) = v0;
                *(float4*)(g_zb    + (size_t)r * HD + tx * 4) = v1;
            }
        }

        if (next < ntiles) CP_WAIT0();
        __syncthreads();                           // buffer handoff
        tile = next; buf ^= 1;
    }
}

// ---------------- aggregation + tanh residual update (warp per node) ---------
__global__ void __launch_bounds__(256) agg_update_kernel(int N) {
    int node = (blockIdx.x * blockDim.x + threadIdx.x) >> 5;
    int lane = threadIdx.x & 31;
    if (node >= N) return;
    const float4* neigh = (const float4*)g_neigh;
    const float4* zb    = (const float4*)g_zb;
    float4*       hv    = (float4*)g_h;

    int s = g_rowstart[node];
    int e = g_rowstart[node + 1];
    float4 acc = make_float4(0.f, 0.f, 0.f, 0.f);
    int i = s;
    for (; i + 8 <= e; i += 8) {                    // MLP=8 gather
        int2 p[8];
#pragma unroll
        for (int q = 0; q < 8; q++) p[q] = g_epack[i + q];
        float4 v[8];
#pragma unroll
        for (int q = 0; q < 8; q++) v[q] = neigh[(size_t)p[q].x * 32 + lane];
#pragma unroll
        for (int q = 0; q < 8; q++) {
            float w = __int_as_float(p[q].y);
            acc.x += w * v[q].x; acc.y += w * v[q].y;
            acc.z += w * v[q].z; acc.w += w * v[q].w;
        }
    }
    for (; i + 2 <= e; i += 2) {
        int2 p0 = g_epack[i], p1 = g_epack[i + 1];
        float4 v0 = neigh[(size_t)p0.x * 32 + lane];
        float4 v1 = neigh[(size_t)p1.x * 32 + lane];
        float w0 = __int_as_float(p0.y), w1 = __int_as_float(p1.y);
        acc.x += w0*v0.x + w1*v1.x; acc.y += w0*v0.y + w1*v1.y;
        acc.z += w0*v0.z + w1*v1.z; acc.w += w0*v0.w + w1*v1.w;
    }
    for (; i < e; i++) {
        int2 p = g_epack[i];
        float w = __int_as_float(p.y);
        float4 v = neigh[(size_t)p.x * 32 + lane];
        acc.x += w * v.x; acc.y += w * v.y; acc.z += w * v.z; acc.w += w * v.w;
    }
    float4 c = zb[(size_t)node * 32 + lane];
    c.x += acc.x; c.y += acc.y; c.z += acc.z; c.w += acc.w;
    float4 xo = hv[(size_t)node * 32 + lane];
    xo.x += EPS_C * tanh_fast(c.x);
    xo.y += EPS_C * tanh_fast(c.y);
    xo.z += EPS_C * tanh_fast(c.z);
    xo.w += EPS_C * tanh_fast(c.w);
    hv[(size_t)node * 32 + lane] = xo;
}

// ---------------- readout: out[M x 40] = h @ W_out^T + b_out -----------------
__global__ void __launch_bounds__(128) readout_kernel(const float* __restrict__ W,
                                                      const float* __restrict__ b,
                                                      float* __restrict__ out,
                                                      int M) {
    __shared__ float hs[32 * 132];
    __shared__ float Wt[128 * 41];
    int tid = threadIdx.x;
    int row0 = blockIdx.x * 32;
#pragma unroll
    for (int j = 0; j < 8; j++) {
        int f = tid + j * 128;
        int r = f >> 5;
        int c = (f & 31) << 2;
        float4 v = make_float4(0.f, 0.f, 0.f, 0.f);
        if (row0 + r < M) v = *(const float4*)(g_h + (size_t)(row0 + r) * HD + c);
        *(float4*)(hs + r * 132 + c) = v;
    }
    for (int f = tid; f < OUTD * HD; f += 128) {
        int c = f / HD, k = f % HD;
        Wt[k * 41 + c] = W[c * HD + k];
    }
    __syncthreads();

    int tx = tid & 7;
    int ty = tid >> 3;
    float acc[2][5] = {{0.f,0.f,0.f,0.f,0.f},{0.f,0.f,0.f,0.f,0.f}};
#pragma unroll 4
    for (int k = 0; k < HD; k++) {
        float a0 = hs[(ty * 2) * 132 + k];
        float a1 = hs[(ty * 2 + 1) * 132 + k];
        const float* w = Wt + k * 41 + tx * 5;
#pragma unroll
        for (int j = 0; j < 5; j++) {
            float wv = w[j];
            acc[0][j] += a0 * wv;
            acc[1][j] += a1 * wv;
        }
    }
#pragma unroll
    for (int i = 0; i < 2; i++) {
        int r = row0 + ty * 2 + i;
        if (r < M) {
#pragma unroll
            for (int j = 0; j < 5; j++)
                out[(size_t)r * OUTD + tx * 5 + j] = acc[i][j] + b[tx * 5 + j];
        }
    }
}

// ---------------- launch ------------------------------------------------------
extern "C" void kernel_launch(void* const* d_in, const int* in_sizes, int n_in,
                              void* d_out, int out_size) {
    const float* x      = (const float*)d_in[0];
    const int*   ei     = (const int*)d_in[1];     // int32 (JAX x64 disabled)
    const float* ew     = (const float*)d_in[2];
    const float* W_emb  = (const float*)d_in[3];
    const float* b_emb  = (const float*)d_in[4];
    const float* W_lin  = (const float*)d_in[5];
    const float* W_anti = (const float*)d_in[6];
    const float* b_conv = (const float*)d_in[7];
    const float* W_out  = (const float*)d_in[8];
    const float* b_out  = (const float*)d_in[9];
    float*       out    = (float*)d_out;

    const int M = in_sizes[0] / HD;
    const int E = in_sizes[2];
    const int gb = (M + 63) / 64;
    const int ntiles = (M + TROWS - 1) / TROWS;

    // one persistent CTA per SM; 224 KB smem opt-in (host calls, capture-legal)
    static int nsm = 0;
    if (!nsm) {
        cudaDeviceGetAttribute(&nsm, cudaDevAttrMultiProcessorCount, 0);
        if (nsm <= 0) nsm = 148;
        cudaFuncSetAttribute((const void*)conv_gemm_kernel,
                             cudaFuncAttributeMaxDynamicSharedMemorySize, CONV_SMEM);
    }

    // Launch order arranged so conv_gemm_kernel is launch #4 (ncu capture slot).
    // (1) weights + rowstart zero
    precompute_kernel<<<64, 256>>>(W_emb, W_lin, W_anti, b_conv, M + 1);
    // (2) degree histogram (needs zeroed rowstart)
    count_kernel<<<(E + 255) / 256, 256>>>(ei, E, M);
    // (3) embedding (needs precompute)
    embed_gemm_kernel<<<gb, 256>>>(x, b_emb, M);
    // (4) first conv (needs embed)  <-- ncu capture lands here
    conv_gemm_kernel<<<nsm, CONV_TB, CONV_SMEM>>>(M, ntiles);
    // (5-7) finish CSR build (scan merged: partial + apply)
    scan_partial_kernel<<<SCAN_NB, 256>>>(M + 1);
    scan_apply_kernel<<<SCAN_NB, 256>>>(M + 1, M);
    sort_kernel<<<(E + 255) / 256, 256>>>(ei, ew, E, M);
    // (8) first aggregation
    agg_update_kernel<<<(M + 7) / 8, 256>>>(M);

    // iterations 2..5
    for (int it = 1; it < NITER; it++) {
        conv_gemm_kernel<<<nsm, CONV_TB, CONV_SMEM>>>(M, ntiles);
        agg_update_kernel<<<(M + 7) / 8, 256>>>(M);
    }

    // readout
    readout_kernel<<<(M + 31) / 32, 128>>>(W_out, b_out, out, M);
}